// round 16
// baseline (speedup 1.0000x reference)
#include <cuda_runtime.h>
#include <cuda_bf16.h>
#include <cstdint>

#define BATCH 4
#define NPIX  4096
#define CDIM  256
#define NPTOT (BATCH * NPIX)   // 16384 pixels total
#define LOG2E 1.4426950408889634f
#define C2SH  57.70780163555853f   // 40 * log2(e)

// Scratch (__device__ globals; allocation-free rule)
__device__ __nv_bfloat16 g_wb [320 * 256];                  // weights bf16
__device__ __nv_bfloat16 g_xb [(size_t)NPTOT * 256];        // xp bf16
__device__ __nv_bfloat16 g_q32[(size_t)NPTOT * 32];         // q bf16 (pre-scaled by log2e)
__device__ __nv_bfloat16 g_k32[(size_t)NPTOT * 32];         // k bf16
__device__ __nv_bfloat16 g_v  [(size_t)NPTOT * CDIM];       // V [pg][c] bf16
__device__ float         g_o  [(size_t)BATCH * CDIM * NPIX];// O transposed [b][c][n]

// ---------------- helpers ----------------
__device__ __forceinline__ uint32_t s2u(const void* p) {
    uint32_t a;
    asm("{ .reg .u64 t; cvta.to.shared.u64 t, %1; cvt.u32.u64 %0, t; }" : "=r"(a) : "l"(p));
    return a;
}
// packs (e0, e1) -> bf16x2 word, e0 in low half
__device__ __forceinline__ uint32_t packbf(float e0, float e1) {
    uint32_t r;
    asm("cvt.rn.satfinite.bf16x2.f32 %0, %1, %2;" : "=r"(r) : "f"(e1), "f"(e0));
    return r;
}
__device__ __forceinline__ float ex2f(float x) {
    float y;
    asm("ex2.approx.ftz.f32 %0, %1;" : "=f"(y) : "f"(x));
    return y;
}
__device__ __forceinline__ void ldsm4(uint32_t* r, uint32_t a) {
    asm volatile("ldmatrix.sync.aligned.m8n8.x4.shared.b16 {%0,%1,%2,%3}, [%4];"
                 : "=r"(r[0]), "=r"(r[1]), "=r"(r[2]), "=r"(r[3]) : "r"(a));
}
__device__ __forceinline__ void ldsm4t(uint32_t* r, uint32_t a) {
    asm volatile("ldmatrix.sync.aligned.m8n8.x4.trans.shared.b16 {%0,%1,%2,%3}, [%4];"
                 : "=r"(r[0]), "=r"(r[1]), "=r"(r[2]), "=r"(r[3]) : "r"(a));
}
__device__ __forceinline__ void mma16816(float* d, const uint32_t* a, uint32_t b0, uint32_t b1) {
    asm volatile("mma.sync.aligned.m16n8k16.row.col.f32.bf16.bf16.f32 "
                 "{%0,%1,%2,%3}, {%4,%5,%6,%7}, {%8,%9}, {%0,%1,%2,%3};"
                 : "+f"(d[0]), "+f"(d[1]), "+f"(d[2]), "+f"(d[3])
                 : "r"(a[0]), "r"(a[1]), "r"(a[2]), "r"(a[3]), "r"(b0), "r"(b1));
}
__device__ __forceinline__ void cpa16(uint32_t dst, const void* src) {
    asm volatile("cp.async.cg.shared.global [%0], [%1], 16;" :: "r"(dst), "l"(src) : "memory");
}
#define CP_COMMIT() asm volatile("cp.async.commit_group;" ::: "memory")

// ---------------------------------------------------------------------------
// Kernel 0: weight bf16 convert (one-time, tiny)
// ---------------------------------------------------------------------------
__global__ __launch_bounds__(256) void wconv_kernel(
    const float* __restrict__ wq, const float* __restrict__ wk,
    const float* __restrict__ wv)
{
    #pragma unroll
    for (int i = 0; i < 4; i++) {
        int e = blockIdx.x * 1024 + i * 256 + threadIdx.x;
        int o = e >> 8, c = e & 255;
        const float* src = (o < 32) ? (wq + o * 256)
                         : (o < 64) ? (wk + (o - 32) * 256)
                                    : (wv + (o - 64) * 256);
        g_wb[e] = __float2bfloat16(src[c]);
    }
}

// ---------------------------------------------------------------------------
// Kernel 1: space-to-depth gather, emit xp bf16.
// ---------------------------------------------------------------------------
__global__ __launch_bounds__(256) void gather_kernel(const float* __restrict__ x)
{
    __shared__ float xs[32][260];
    const int whalf = blockIdx.x, h2 = blockIdx.y, b = blockIdx.z;
    const int t = threadIdx.x;

    #pragma unroll
    for (int i = 0; i < 32; i++) {
        int idx = i * 256 + t;
        int row = idx >> 6, j = idx & 63;
        int ci = row & 63, hi = row >> 6;
        float val = x[(((size_t)(b * 64 + ci) * 128) + (2 * h2 + hi)) * 128 + whalf * 64 + j];
        xs[j >> 1][(j & 1) * 128 + hi * 64 + ci] = val;
    }
    __syncthreads();

    const int p = t >> 3, cg = t & 7;
    const size_t pg = (size_t)b * NPIX + h2 * 64 + whalf * 32 + p;
    uint32_t* dh = (uint32_t*)(g_xb + pg * 256);
    #pragma unroll
    for (int i = 0; i < 16; i++) {
        int u = cg + i * 8;
        dh[u] = packbf(xs[p][u * 2], xs[p][u * 2 + 1]);
    }
}

// ---------------------------------------------------------------------------
// Kernel 2: projections, single-product bf16 HMMA.  CTA 128 px x 64 out,
// K=256/32, double buffer.  q outputs scaled by log2e for ex2-softmax.
// ---------------------------------------------------------------------------
#define PG_AS   40
#define PG_ABUF (128 * PG_AS)
#define PG_BBUF (64 * PG_AS)
#define PG_STAGE (PG_ABUF + PG_BBUF)
#define PG_SMEM (2 * PG_STAGE * 2)       // 30720 bytes

__global__ __launch_bounds__(256, 2) void projgemm_kernel(
    const float* __restrict__ bq, const float* __restrict__ bk,
    const float* __restrict__ bv)
{
    extern __shared__ __nv_bfloat16 pgs[];
    const int ptile = blockIdx.x, otile = blockIdx.y;
    const int t = threadIdx.x, lane = t & 31, wid = t >> 5;
    const int warp_r = wid >> 2, warp_o = wid & 3;

    auto issue = [&](int kc, int s) {
        __nv_bfloat16* A = pgs + s * PG_STAGE;
        __nv_bfloat16* B = A + PG_ABUF;
        #pragma unroll
        for (int i = 0; i < 2; i++) {
            int idx = i * 256 + t;
            int row = idx >> 2, c16 = idx & 3;
            cpa16(s2u(A + row * PG_AS + c16 * 8),
                  g_xb + (size_t)(ptile * 128 + row) * 256 + kc * 32 + c16 * 8);
        }
        {
            int row = t >> 2, c16 = t & 3;
            cpa16(s2u(B + row * PG_AS + c16 * 8),
                  g_wb + (size_t)(otile * 64 + row) * 256 + kc * 32 + c16 * 8);
        }
        CP_COMMIT();
    };

    float acc[4][2][4];
    #pragma unroll
    for (int mi = 0; mi < 4; mi++)
        #pragma unroll
        for (int ni = 0; ni < 2; ni++)
            #pragma unroll
            for (int i = 0; i < 4; i++) acc[mi][ni][i] = 0.0f;

    issue(0, 0);
    for (int kc = 0; kc < 8; kc++) {
        if (kc < 7) issue(kc + 1, (kc + 1) & 1);
        if (kc < 7) asm volatile("cp.async.wait_group 1;" ::: "memory");
        else        asm volatile("cp.async.wait_group 0;" ::: "memory");
        __syncthreads();
        __nv_bfloat16* A = pgs + (kc & 1) * PG_STAGE;
        __nv_bfloat16* B = A + PG_ABUF;
        #pragma unroll
        for (int k16 = 0; k16 < 2; k16++) {
            const int kb = k16 * 16 + ((lane >> 4) << 3);
            uint32_t Af[4][4], Bf[4];
            #pragma unroll
            for (int mi = 0; mi < 4; mi++)
                ldsm4(Af[mi], s2u(A + (warp_r * 64 + mi * 16 + (lane & 15)) * PG_AS + kb));
            ldsm4(Bf, s2u(B + (warp_o * 16 + (lane & 15)) * PG_AS + kb));
            #pragma unroll
            for (int mi = 0; mi < 4; mi++)
                #pragma unroll
                for (int ni = 0; ni < 2; ni++)
                    mma16816(acc[mi][ni], Af[mi], Bf[ni], Bf[ni + 2]);
        }
        __syncthreads();
    }

    // epilogue: add bias, route to q/k (bf16, 32-wide) or v (bf16)
    #pragma unroll
    for (int mi = 0; mi < 4; mi++) {
        int px = warp_r * 64 + mi * 16 + (lane >> 2);
        size_t pg0 = (size_t)ptile * 128 + px;
        size_t pg1 = pg0 + 8;
        #pragma unroll
        for (int ni = 0; ni < 2; ni++) {
            int c = warp_o * 16 + ni * 8 + (lane & 3) * 2;
            int o = otile * 64 + c;
            float b0, b1;
            if (o < 32)      { b0 = bq[o];      b1 = bq[o + 1]; }
            else if (o < 64) { b0 = bk[o - 32]; b1 = bk[o - 31]; }
            else             { b0 = bv[o - 64]; b1 = bv[o - 63]; }
            float v00 = acc[mi][ni][0] + b0, v01 = acc[mi][ni][1] + b1;
            float v10 = acc[mi][ni][2] + b0, v11 = acc[mi][ni][3] + b1;
            if (otile == 0) {
                if (o < 32) {   // q: pre-scale by log2e for ex2-softmax
                    v00 *= LOG2E; v01 *= LOG2E; v10 *= LOG2E; v11 *= LOG2E;
                }
                uint32_t* dst = (o < 32) ? (uint32_t*)g_q32 : (uint32_t*)g_k32;
                int oo = (o & 31) >> 1;
                dst[pg0 * 16 + oo] = packbf(v00, v01);
                dst[pg1 * 16 + oo] = packbf(v10, v11);
            } else {
                int cv = o - 64;
                *(uint32_t*)(g_v + pg0 * 256 + cv) = packbf(v00, v01);
                *(uint32_t*)(g_v + pg1 * 256 + cv) = packbf(v10, v11);
            }
        }
    }
}

// ---------------------------------------------------------------------------
// Kernel 3: FUSED flash attention.  CTA = 128 rows x 128-ch half.
// CHANGED vs R15: mt body split into two m-halves E0->PV0->E1->PV1 with
// 32-reg acc_e halves — E1 is independent of PV0, so ptxas can interleave
// tensor/ldsm streams (dual-roofline overlap).  De-phasing removed.
// ---------------------------------------------------------------------------
#define FA_SQ   0
#define FA_K0   5120               // bf16 offsets
#define FA_K1   10240
#define FA_V0   15360
#define FA_V1   (15360 + 17408)
#define FA_SMEM ((15360 + 2 * 17408) * 2)   // 100352 bytes

__global__ __launch_bounds__(256, 1) void fattn_kernel()
{
    extern __shared__ __align__(16) __nv_bfloat16 fsm[];
    const int n0 = blockIdx.x * 128;
    const int half = blockIdx.y;
    const int b = blockIdx.z;
    const int t = threadIdx.x, lane = t & 31, wid = t >> 5;
    __nv_bfloat16* sQ = fsm + FA_SQ;

    // load Q rows (32 bf16 each) into sQ, stride 40
    {
        const uint4* qs = (const uint4*)(g_q32 + (size_t)(b * NPIX + n0) * 32);
        #pragma unroll
        for (int i = 0; i < 2; i++) {
            int idx = i * 256 + t;
            int row = idx >> 2, c16 = idx & 3;
            *(uint4*)(sQ + row * 40 + c16 * 8) = qs[row * 4 + c16];
        }
    }

    auto issueKV = [&](int mt, int s) {
        __nv_bfloat16* dK = fsm + (s ? FA_K1 : FA_K0);
        __nv_bfloat16* dV = fsm + (s ? FA_V1 : FA_V0);
        #pragma unroll
        for (int i = 0; i < 2; i++) {
            int idx = i * 256 + t;
            int row = idx >> 2, c16 = idx & 3;
            cpa16(s2u(dK + row * 40 + c16 * 8),
                  g_k32 + (size_t)(b * NPIX + mt * 128 + row) * 32 + c16 * 8);
        }
        #pragma unroll
        for (int i = 0; i < 8; i++) {
            int idx = i * 256 + t;
            int row = idx >> 4, c8 = idx & 15;
            cpa16(s2u(dV + row * 136 + c8 * 8),
                  g_v + (size_t)(b * NPIX + mt * 128 + row) * 256 + half * 128 + c8 * 8);
        }
        CP_COMMIT();
    };

    issueKV(0, 0);
    __syncthreads();   // sQ visible

    // hoisted per-lane byte offsets (smem addresses)
    const uint32_t fsb  = s2u(fsm);
    const uint32_t offK = (uint32_t)(lane & 15) * 80 + ((lane >> 4) << 4);
    const uint32_t offV = (uint32_t)((lane & 7) + ((lane >> 4) << 3)) * 272
                        + ((lane >> 3) & 1) * 16;
    const uint32_t kbuf0 = fsb + FA_K0 * 2 + offK, kbuf1 = fsb + FA_K1 * 2 + offK;
    const uint32_t vbuf0 = fsb + FA_V0 * 2 + offV, vbuf1 = fsb + FA_V1 * 2 + offV;

    uint32_t Aq[2][4];
    #pragma unroll
    for (int k16 = 0; k16 < 2; k16++)
        ldsm4(Aq[k16], fsb + (uint32_t)(wid * 16 + (lane & 15)) * 80
                           + k16 * 32 + ((lane >> 4) << 4));

    float acc_o[16][4];
    #pragma unroll
    for (int ni = 0; ni < 16; ni++)
        #pragma unroll
        for (int i = 0; i < 4; i++) acc_o[ni][i] = 0.0f;
    float s0 = 0.0f, s1 = 0.0f;

    for (int mt = 0; mt < 32; mt++) {
        if (mt < 31) {
            issueKV(mt + 1, (mt + 1) & 1);
            asm volatile("cp.async.wait_group 1;" ::: "memory");
        } else {
            asm volatile("cp.async.wait_group 0;" ::: "memory");
        }
        __syncthreads();
        const uint32_t cKb = (mt & 1) ? kbuf1 : kbuf0;
        const uint32_t cVb = (mt & 1) ? vbuf1 : vbuf0;

        // m-half pipeline: E(h) then PV(h); E(h=1) independent of PV(h=0)
        float eH[2][8][4];
        #pragma unroll
        for (int h = 0; h < 2; h++) {
            // ---- E half: m-cols h*64 .. h*64+63 (nj = h*4 .. h*4+3) ----
            #pragma unroll
            for (int ni = 0; ni < 8; ni++)
                #pragma unroll
                for (int i = 0; i < 4; i++) eH[h][ni][i] = 0.0f;
            #pragma unroll
            for (int k16 = 0; k16 < 2; k16++) {
                uint32_t Bm[4][4];
                #pragma unroll
                for (int nj = 0; nj < 4; nj++)
                    ldsm4(Bm[nj], cKb + (h * 4 + nj) * 1280u + k16 * 32u);
                #pragma unroll
                for (int ni = 0; ni < 8; ni++)
                    mma16816(eH[h][ni], Aq[k16], Bm[ni >> 1][ni & 1], Bm[ni >> 1][(ni & 1) + 2]);
            }
            // ---- PV half: j = h*4 .. h*4+3 ----
            #pragma unroll
            for (int jl = 0; jl < 4; jl++) {
                const int jg = h * 4 + jl;
                uint32_t Bv[8][4];
                #pragma unroll
                for (int nj = 0; nj < 8; nj++)
                    ldsm4t(Bv[nj], cVb + jg * 4352u + nj * 32u);
                float e0 = ex2f(eH[h][2 * jl][0] - C2SH);
                float e1 = ex2f(eH[h][2 * jl][1] - C2SH);
                float e2 = ex2f(eH[h][2 * jl][2] - C2SH);
                float e3 = ex2f(eH[h][2 * jl][3] - C2SH);
                float f0 = ex2f(eH[h][2 * jl + 1][0] - C2SH);
                float f1 = ex2f(eH[h][2 * jl + 1][1] - C2SH);
                float f2 = ex2f(eH[h][2 * jl + 1][2] - C2SH);
                float f3 = ex2f(eH[h][2 * jl + 1][3] - C2SH);
                s0 += (e0 + e1) + (f0 + f1);
                s1 += (e2 + e3) + (f2 + f3);
                uint32_t Af[4];
                Af[0] = packbf(e0, e1);
                Af[1] = packbf(e2, e3);
                Af[2] = packbf(f0, f1);
                Af[3] = packbf(f2, f3);
                #pragma unroll
                for (int ni = 0; ni < 16; ni++)
                    mma16816(acc_o[ni], Af, Bv[ni >> 1][ni & 1], Bv[ni >> 1][(ni & 1) + 2]);
            }
        }
        __syncthreads();
    }

    // ---- normalize + transpose to g_o[b][c][n] ----
    s0 += __shfl_xor_sync(0xffffffffu, s0, 1);
    s0 += __shfl_xor_sync(0xffffffffu, s0, 2);
    s1 += __shfl_xor_sync(0xffffffffu, s1, 1);
    s1 += __shfl_xor_sync(0xffffffffu, s1, 2);
    const float li0 = 1.0f / s0, li1 = 1.0f / s1;

    float* sT = (float*)fsm;   // [128 ch][132 row-stride] = 67584 B
    const int r = wid * 16 + (lane >> 2);
    #pragma unroll
    for (int ni = 0; ni < 16; ni++) {
        int c = ni * 8 + (lane & 3) * 2;
        sT[c * 132 + r]           = acc_o[ni][0] * li0;
        sT[(c + 1) * 132 + r]     = acc_o[ni][1] * li0;
        sT[c * 132 + r + 8]       = acc_o[ni][2] * li1;
        sT[(c + 1) * 132 + r + 8] = acc_o[ni][3] * li1;
    }
    __syncthreads();
    #pragma unroll
    for (int i = 0; i < 16; i++) {
        int idx = i * 256 + t;
        int c = idx >> 5, colg = idx & 31;
        float4 v = *(float4*)(sT + c * 132 + colg * 4);
        *(float4*)(g_o + ((size_t)(b * 256 + half * 128 + c)) * 4096 + n0 + colg * 4) = v;
    }
}

// ---------------------------------------------------------------------------
// Kernel 4: epilogue gamma*O + xp, depth-to-space (g_o reads coalesced).
// ---------------------------------------------------------------------------
__global__ __launch_bounds__(256) void epi_kernel(
    const float* __restrict__ x, const float* __restrict__ gamma,
    float* __restrict__ out)
{
    int idx = blockIdx.x * 256 + threadIdx.x;
    int w = idx & 127, h = (idx >> 7) & 127, ci = (idx >> 14) & 63, b = idx >> 20;
    int CC = (w & 1) * 128 + (h & 1) * 64 + ci;
    int n = (h >> 1) * 64 + (w >> 1);
    out[idx] = __ldg(gamma) * g_o[((size_t)(b * 256 + CC)) * 4096 + n] + x[idx];
}

// ---------------------------------------------------------------------------
extern "C" void kernel_launch(void* const* d_in, const int* in_sizes, int n_in,
                              void* d_out, int out_size)
{
    const float* x     = (const float*)d_in[0];
    const float* wq    = (const float*)d_in[1];
    const float* bq    = (const float*)d_in[2];
    const float* wk    = (const float*)d_in[3];
    const float* bk    = (const float*)d_in[4];
    const float* wv    = (const float*)d_in[5];
    const float* bv    = (const float*)d_in[6];
    const float* gamma = (const float*)d_in[7];
    float* out = (float*)d_out;
    (void)in_sizes; (void)n_in; (void)out_size;

    cudaFuncSetAttribute(projgemm_kernel, cudaFuncAttributeMaxDynamicSharedMemorySize, PG_SMEM);
    cudaFuncSetAttribute(fattn_kernel,    cudaFuncAttributeMaxDynamicSharedMemorySize, FA_SMEM);

    wconv_kernel<<<80, 256>>>(wq, wk, wv);

    dim3 ggrid(2, 64, BATCH);
    gather_kernel<<<ggrid, 256>>>(x);

    dim3 pggrid(NPTOT / 128, 5);
    projgemm_kernel<<<pggrid, 256, PG_SMEM>>>(bq, bk, bv);

    dim3 fgrid(NPIX / 128, 2, BATCH);
    fattn_kernel<<<fgrid, 256, FA_SMEM>>>();

    epi_kernel<<<(BATCH * 64 * 128 * 128) / 256, 256>>>(x, gamma, out);
}

// round 17
// speedup vs baseline: 1.5206x; 1.5206x over previous
#include <cuda_runtime.h>
#include <cuda_bf16.h>
#include <cstdint>

#define BATCH 4
#define NPIX  4096
#define CDIM  256
#define NPTOT (BATCH * NPIX)   // 16384 pixels total
#define LOG2E 1.4426950408889634f
#define C2SH  57.70780163555853f   // 40 * log2(e)

// Scratch (__device__ globals; allocation-free rule)
__device__ __nv_bfloat16 g_wb [320 * 256];                  // weights bf16
__device__ __nv_bfloat16 g_xb [(size_t)NPTOT * 256];        // xp bf16
__device__ __nv_bfloat16 g_q32[(size_t)NPTOT * 32];         // q bf16 (pre-scaled by log2e)
__device__ __nv_bfloat16 g_k32[(size_t)NPTOT * 32];         // k bf16
__device__ __nv_bfloat16 g_v  [(size_t)NPTOT * CDIM];       // V [pg][c] bf16
__device__ float         g_o  [(size_t)BATCH * CDIM * NPIX];// O transposed [b][c][n]

// ---------------- helpers ----------------
__device__ __forceinline__ uint32_t s2u(const void* p) {
    uint32_t a;
    asm("{ .reg .u64 t; cvta.to.shared.u64 t, %1; cvt.u32.u64 %0, t; }" : "=r"(a) : "l"(p));
    return a;
}
// packs (e0, e1) -> bf16x2 word, e0 in low half
__device__ __forceinline__ uint32_t packbf(float e0, float e1) {
    uint32_t r;
    asm("cvt.rn.satfinite.bf16x2.f32 %0, %1, %2;" : "=r"(r) : "f"(e1), "f"(e0));
    return r;
}
__device__ __forceinline__ float ex2f(float x) {
    float y;
    asm("ex2.approx.ftz.f32 %0, %1;" : "=f"(y) : "f"(x));
    return y;
}
__device__ __forceinline__ void ldsm4(uint32_t* r, uint32_t a) {
    asm volatile("ldmatrix.sync.aligned.m8n8.x4.shared.b16 {%0,%1,%2,%3}, [%4];"
                 : "=r"(r[0]), "=r"(r[1]), "=r"(r[2]), "=r"(r[3]) : "r"(a));
}
__device__ __forceinline__ void ldsm4t(uint32_t* r, uint32_t a) {
    asm volatile("ldmatrix.sync.aligned.m8n8.x4.trans.shared.b16 {%0,%1,%2,%3}, [%4];"
                 : "=r"(r[0]), "=r"(r[1]), "=r"(r[2]), "=r"(r[3]) : "r"(a));
}
__device__ __forceinline__ void ldsm2t(uint32_t* r, uint32_t a) {
    asm volatile("ldmatrix.sync.aligned.m8n8.x2.trans.shared.b16 {%0,%1}, [%2];"
                 : "=r"(r[0]), "=r"(r[1]) : "r"(a));
}
__device__ __forceinline__ void mma16816(float* d, const uint32_t* a, uint32_t b0, uint32_t b1) {
    asm volatile("mma.sync.aligned.m16n8k16.row.col.f32.bf16.bf16.f32 "
                 "{%0,%1,%2,%3}, {%4,%5,%6,%7}, {%8,%9}, {%0,%1,%2,%3};"
                 : "+f"(d[0]), "+f"(d[1]), "+f"(d[2]), "+f"(d[3])
                 : "r"(a[0]), "r"(a[1]), "r"(a[2]), "r"(a[3]), "r"(b0), "r"(b1));
}
__device__ __forceinline__ void cpa16(uint32_t dst, const void* src) {
    asm volatile("cp.async.cg.shared.global [%0], [%1], 16;" :: "r"(dst), "l"(src) : "memory");
}
#define CP_COMMIT() asm volatile("cp.async.commit_group;" ::: "memory")

// ---------------------------------------------------------------------------
// Kernel 0: weight bf16 convert (one-time, tiny)
// ---------------------------------------------------------------------------
__global__ __launch_bounds__(256) void wconv_kernel(
    const float* __restrict__ wq, const float* __restrict__ wk,
    const float* __restrict__ wv)
{
    #pragma unroll
    for (int i = 0; i < 4; i++) {
        int e = blockIdx.x * 1024 + i * 256 + threadIdx.x;
        int o = e >> 8, c = e & 255;
        const float* src = (o < 32) ? (wq + o * 256)
                         : (o < 64) ? (wk + (o - 32) * 256)
                                    : (wv + (o - 64) * 256);
        g_wb[e] = __float2bfloat16(src[c]);
    }
}

// ---------------------------------------------------------------------------
// Kernel 1: space-to-depth gather, emit xp bf16.
// ---------------------------------------------------------------------------
__global__ __launch_bounds__(256) void gather_kernel(const float* __restrict__ x)
{
    __shared__ float xs[32][260];
    const int whalf = blockIdx.x, h2 = blockIdx.y, b = blockIdx.z;
    const int t = threadIdx.x;

    #pragma unroll
    for (int i = 0; i < 32; i++) {
        int idx = i * 256 + t;
        int row = idx >> 6, j = idx & 63;
        int ci = row & 63, hi = row >> 6;
        float val = x[(((size_t)(b * 64 + ci) * 128) + (2 * h2 + hi)) * 128 + whalf * 64 + j];
        xs[j >> 1][(j & 1) * 128 + hi * 64 + ci] = val;
    }
    __syncthreads();

    const int p = t >> 3, cg = t & 7;
    const size_t pg = (size_t)b * NPIX + h2 * 64 + whalf * 32 + p;
    uint32_t* dh = (uint32_t*)(g_xb + pg * 256);
    #pragma unroll
    for (int i = 0; i < 16; i++) {
        int u = cg + i * 8;
        dh[u] = packbf(xs[p][u * 2], xs[p][u * 2 + 1]);
    }
}

// ---------------------------------------------------------------------------
// Kernel 2: projections, single-product bf16 HMMA.  CTA 128 px x 64 out,
// K=256/32, double buffer.  q outputs scaled by log2e for ex2-softmax.
// ---------------------------------------------------------------------------
#define PG_AS   40
#define PG_ABUF (128 * PG_AS)
#define PG_BBUF (64 * PG_AS)
#define PG_STAGE (PG_ABUF + PG_BBUF)
#define PG_SMEM (2 * PG_STAGE * 2)       // 30720 bytes

__global__ __launch_bounds__(256, 2) void projgemm_kernel(
    const float* __restrict__ bq, const float* __restrict__ bk,
    const float* __restrict__ bv)
{
    extern __shared__ __nv_bfloat16 pgs[];
    const int ptile = blockIdx.x, otile = blockIdx.y;
    const int t = threadIdx.x, lane = t & 31, wid = t >> 5;
    const int warp_r = wid >> 2, warp_o = wid & 3;

    auto issue = [&](int kc, int s) {
        __nv_bfloat16* A = pgs + s * PG_STAGE;
        __nv_bfloat16* B = A + PG_ABUF;
        #pragma unroll
        for (int i = 0; i < 2; i++) {
            int idx = i * 256 + t;
            int row = idx >> 2, c16 = idx & 3;
            cpa16(s2u(A + row * PG_AS + c16 * 8),
                  g_xb + (size_t)(ptile * 128 + row) * 256 + kc * 32 + c16 * 8);
        }
        {
            int row = t >> 2, c16 = t & 3;
            cpa16(s2u(B + row * PG_AS + c16 * 8),
                  g_wb + (size_t)(otile * 64 + row) * 256 + kc * 32 + c16 * 8);
        }
        CP_COMMIT();
    };

    float acc[4][2][4];
    #pragma unroll
    for (int mi = 0; mi < 4; mi++)
        #pragma unroll
        for (int ni = 0; ni < 2; ni++)
            #pragma unroll
            for (int i = 0; i < 4; i++) acc[mi][ni][i] = 0.0f;

    issue(0, 0);
    for (int kc = 0; kc < 8; kc++) {
        if (kc < 7) issue(kc + 1, (kc + 1) & 1);
        if (kc < 7) asm volatile("cp.async.wait_group 1;" ::: "memory");
        else        asm volatile("cp.async.wait_group 0;" ::: "memory");
        __syncthreads();
        __nv_bfloat16* A = pgs + (kc & 1) * PG_STAGE;
        __nv_bfloat16* B = A + PG_ABUF;
        #pragma unroll
        for (int k16 = 0; k16 < 2; k16++) {
            const int kb = k16 * 16 + ((lane >> 4) << 3);
            uint32_t Af[4][4], Bf[4];
            #pragma unroll
            for (int mi = 0; mi < 4; mi++)
                ldsm4(Af[mi], s2u(A + (warp_r * 64 + mi * 16 + (lane & 15)) * PG_AS + kb));
            ldsm4(Bf, s2u(B + (warp_o * 16 + (lane & 15)) * PG_AS + kb));
            #pragma unroll
            for (int mi = 0; mi < 4; mi++)
                #pragma unroll
                for (int ni = 0; ni < 2; ni++)
                    mma16816(acc[mi][ni], Af[mi], Bf[ni], Bf[ni + 2]);
        }
        __syncthreads();
    }

    // epilogue: add bias, route to q/k (bf16, 32-wide) or v (bf16)
    #pragma unroll
    for (int mi = 0; mi < 4; mi++) {
        int px = warp_r * 64 + mi * 16 + (lane >> 2);
        size_t pg0 = (size_t)ptile * 128 + px;
        size_t pg1 = pg0 + 8;
        #pragma unroll
        for (int ni = 0; ni < 2; ni++) {
            int c = warp_o * 16 + ni * 8 + (lane & 3) * 2;
            int o = otile * 64 + c;
            float b0, b1;
            if (o < 32)      { b0 = bq[o];      b1 = bq[o + 1]; }
            else if (o < 64) { b0 = bk[o - 32]; b1 = bk[o - 31]; }
            else             { b0 = bv[o - 64]; b1 = bv[o - 63]; }
            float v00 = acc[mi][ni][0] + b0, v01 = acc[mi][ni][1] + b1;
            float v10 = acc[mi][ni][2] + b0, v11 = acc[mi][ni][3] + b1;
            if (otile == 0) {
                if (o < 32) {   // q: pre-scale by log2e for ex2-softmax
                    v00 *= LOG2E; v01 *= LOG2E; v10 *= LOG2E; v11 *= LOG2E;
                }
                uint32_t* dst = (o < 32) ? (uint32_t*)g_q32 : (uint32_t*)g_k32;
                int oo = (o & 31) >> 1;
                dst[pg0 * 16 + oo] = packbf(v00, v01);
                dst[pg1 * 16 + oo] = packbf(v10, v11);
            } else {
                int cv = o - 64;
                *(uint32_t*)(g_v + pg0 * 256 + cv) = packbf(v00, v01);
                *(uint32_t*)(g_v + pg1 * 256 + cv) = packbf(v10, v11);
            }
        }
    }
}

// ---------------------------------------------------------------------------
// Kernel 3: FUSED flash attention.  CTA = 128 rows x 128-ch half.
// R14 loop structure (measured fastest).  NEW: row sums via ones-column in
// V's smem padding (col 128 = 1.0) -> one extra n8 MMA per j accumulates
// sum(p) in acc_s; deletes all per-element FADDs and the shfl reduction.
// ---------------------------------------------------------------------------
#define FA_SQ   0
#define FA_K0   5120               // bf16 offsets
#define FA_K1   10240
#define FA_V0   15360
#define FA_V1   (15360 + 17408)
#define FA_SMEM ((15360 + 2 * 17408) * 2)   // 100352 bytes

__global__ __launch_bounds__(256, 1) void fattn_kernel()
{
    extern __shared__ __align__(16) __nv_bfloat16 fsm[];
    const int n0 = blockIdx.x * 128;
    const int half = blockIdx.y;
    const int b = blockIdx.z;
    const int t = threadIdx.x, lane = t & 31, wid = t >> 5;
    __nv_bfloat16* sQ = fsm + FA_SQ;

    // load Q rows (32 bf16 each) into sQ, stride 40
    {
        const uint4* qs = (const uint4*)(g_q32 + (size_t)(b * NPIX + n0) * 32);
        #pragma unroll
        for (int i = 0; i < 2; i++) {
            int idx = i * 256 + t;
            int row = idx >> 2, c16 = idx & 3;
            *(uint4*)(sQ + row * 40 + c16 * 8) = qs[row * 4 + c16];
        }
    }
    // init V padding: col 128 = 1.0, cols 129..135 = 0 (both buffers).
    // cp.async only writes cols 0..127, so this persists across the loop.
    {
        int row = t & 127, buf = t >> 7;
        __nv_bfloat16* pad = fsm + (buf ? FA_V1 : FA_V0) + row * 136 + 128;
        *(uint4*)pad = make_uint4(0x00003F80u, 0u, 0u, 0u);
    }

    auto issueKV = [&](int mt, int s) {
        __nv_bfloat16* dK = fsm + (s ? FA_K1 : FA_K0);
        __nv_bfloat16* dV = fsm + (s ? FA_V1 : FA_V0);
        #pragma unroll
        for (int i = 0; i < 2; i++) {
            int idx = i * 256 + t;
            int row = idx >> 2, c16 = idx & 3;
            cpa16(s2u(dK + row * 40 + c16 * 8),
                  g_k32 + (size_t)(b * NPIX + mt * 128 + row) * 32 + c16 * 8);
        }
        #pragma unroll
        for (int i = 0; i < 8; i++) {
            int idx = i * 256 + t;
            int row = idx >> 4, c8 = idx & 15;
            cpa16(s2u(dV + row * 136 + c8 * 8),
                  g_v + (size_t)(b * NPIX + mt * 128 + row) * 256 + half * 128 + c8 * 8);
        }
        CP_COMMIT();
    };

    issueKV(0, 0);
    __syncthreads();   // sQ + V padding visible

    // hoisted per-lane byte offsets (smem addresses)
    const uint32_t fsb  = s2u(fsm);
    const uint32_t offK = (uint32_t)(lane & 15) * 80 + ((lane >> 4) << 4);
    const uint32_t offV = (uint32_t)((lane & 7) + ((lane >> 4) << 3)) * 272
                        + ((lane >> 3) & 1) * 16;
    const uint32_t offS = (uint32_t)(lane & 15) * 272 + 256;   // ones column
    const uint32_t kbuf0 = fsb + FA_K0 * 2 + offK, kbuf1 = fsb + FA_K1 * 2 + offK;
    const uint32_t vbuf0 = fsb + FA_V0 * 2 + offV, vbuf1 = fsb + FA_V1 * 2 + offV;
    const uint32_t sbuf0 = fsb + FA_V0 * 2 + offS, sbuf1 = fsb + FA_V1 * 2 + offS;

    uint32_t Aq[2][4];
    #pragma unroll
    for (int k16 = 0; k16 < 2; k16++)
        ldsm4(Aq[k16], fsb + (uint32_t)(wid * 16 + (lane & 15)) * 80
                           + k16 * 32 + ((lane >> 4) << 4));

    float acc_o[16][4];
    #pragma unroll
    for (int ni = 0; ni < 16; ni++)
        #pragma unroll
        for (int i = 0; i < 4; i++) acc_o[ni][i] = 0.0f;
    float acc_s[4] = {0.0f, 0.0f, 0.0f, 0.0f};

    for (int mt = 0; mt < 32; mt++) {
        if (mt < 31) {
            issueKV(mt + 1, (mt + 1) & 1);
            asm volatile("cp.async.wait_group 1;" ::: "memory");
        } else {
            asm volatile("cp.async.wait_group 0;" ::: "memory");
        }
        __syncthreads();
        const uint32_t cKb = (mt & 1) ? kbuf1 : kbuf0;
        const uint32_t cVb = (mt & 1) ? vbuf1 : vbuf0;
        const uint32_t cSb = (mt & 1) ? sbuf1 : sbuf0;

        // ---- E = Q . K^T  (16 rows x 128 m per warp), log2-domain ----
        float acc_e[16][4];
        #pragma unroll
        for (int ni = 0; ni < 16; ni++)
            #pragma unroll
            for (int i = 0; i < 4; i++) acc_e[ni][i] = 0.0f;
        #pragma unroll
        for (int k16 = 0; k16 < 2; k16++) {
            uint32_t Bm[8][4];
            #pragma unroll
            for (int nj = 0; nj < 8; nj++)
                ldsm4(Bm[nj], cKb + nj * 1280u + k16 * 32u);
            #pragma unroll
            for (int ni = 0; ni < 16; ni++)
                mma16816(acc_e[ni], Aq[k16], Bm[ni >> 1][ni & 1], Bm[ni >> 1][(ni & 1) + 2]);
        }

        // ---- per j: exp (ex2) -> P fragment -> O += P.V (+ sum column) ----
        #pragma unroll
        for (int j = 0; j < 8; j++) {
            uint32_t Bv[8][4];
            #pragma unroll
            for (int nj = 0; nj < 8; nj++)
                ldsm4t(Bv[nj], cVb + j * 4352u + nj * 32u);
            uint32_t Bs[2];
            ldsm2t(Bs, cSb + j * 4352u);

            float e0 = ex2f(acc_e[2 * j][0] - C2SH);
            float e1 = ex2f(acc_e[2 * j][1] - C2SH);
            float e2 = ex2f(acc_e[2 * j][2] - C2SH);
            float e3 = ex2f(acc_e[2 * j][3] - C2SH);
            float f0 = ex2f(acc_e[2 * j + 1][0] - C2SH);
            float f1 = ex2f(acc_e[2 * j + 1][1] - C2SH);
            float f2 = ex2f(acc_e[2 * j + 1][2] - C2SH);
            float f3 = ex2f(acc_e[2 * j + 1][3] - C2SH);
            uint32_t Af[4];
            Af[0] = packbf(e0, e1);
            Af[1] = packbf(e2, e3);
            Af[2] = packbf(f0, f1);
            Af[3] = packbf(f2, f3);

            #pragma unroll
            for (int ni = 0; ni < 16; ni++)
                mma16816(acc_o[ni], Af, Bv[ni >> 1][ni & 1], Bv[ni >> 1][(ni & 1) + 2]);
            mma16816(acc_s, Af, Bs[0], Bs[1]);   // row sums (ones column)
        }
        __syncthreads();
    }

    // ---- extract row sums (tile col 0 held by lanes with lane&3==0) ----
    const float s0 = __shfl_sync(0xffffffffu, acc_s[0], lane & 28);
    const float s1 = __shfl_sync(0xffffffffu, acc_s[2], lane & 28);
    const float li0 = 1.0f / s0, li1 = 1.0f / s1;

    // ---- normalize + transpose to g_o[b][c][n] ----
    float* sT = (float*)fsm;   // [128 ch][132 row-stride] = 67584 B
    const int r = wid * 16 + (lane >> 2);
    #pragma unroll
    for (int ni = 0; ni < 16; ni++) {
        int c = ni * 8 + (lane & 3) * 2;
        sT[c * 132 + r]           = acc_o[ni][0] * li0;
        sT[(c + 1) * 132 + r]     = acc_o[ni][1] * li0;
        sT[c * 132 + r + 8]       = acc_o[ni][2] * li1;
        sT[(c + 1) * 132 + r + 8] = acc_o[ni][3] * li1;
    }
    __syncthreads();
    #pragma unroll
    for (int i = 0; i < 16; i++) {
        int idx = i * 256 + t;
        int c = idx >> 5, colg = idx & 31;
        float4 v = *(float4*)(sT + c * 132 + colg * 4);
        *(float4*)(g_o + ((size_t)(b * 256 + half * 128 + c)) * 4096 + n0 + colg * 4) = v;
    }
}

// ---------------------------------------------------------------------------
// Kernel 4: epilogue gamma*O + xp, depth-to-space (g_o reads coalesced).
// ---------------------------------------------------------------------------
__global__ __launch_bounds__(256) void epi_kernel(
    const float* __restrict__ x, const float* __restrict__ gamma,
    float* __restrict__ out)
{
    int idx = blockIdx.x * 256 + threadIdx.x;
    int w = idx & 127, h = (idx >> 7) & 127, ci = (idx >> 14) & 63, b = idx >> 20;
    int CC = (w & 1) * 128 + (h & 1) * 64 + ci;
    int n = (h >> 1) * 64 + (w >> 1);
    out[idx] = __ldg(gamma) * g_o[((size_t)(b * 256 + CC)) * 4096 + n] + x[idx];
}

// ---------------------------------------------------------------------------
extern "C" void kernel_launch(void* const* d_in, const int* in_sizes, int n_in,
                              void* d_out, int out_size)
{
    const float* x     = (const float*)d_in[0];
    const float* wq    = (const float*)d_in[1];
    const float* bq    = (const float*)d_in[2];
    const float* wk    = (const float*)d_in[3];
    const float* bk    = (const float*)d_in[4];
    const float* wv    = (const float*)d_in[5];
    const float* bv    = (const float*)d_in[6];
    const float* gamma = (const float*)d_in[7];
    float* out = (float*)d_out;
    (void)in_sizes; (void)n_in; (void)out_size;

    cudaFuncSetAttribute(projgemm_kernel, cudaFuncAttributeMaxDynamicSharedMemorySize, PG_SMEM);
    cudaFuncSetAttribute(fattn_kernel,    cudaFuncAttributeMaxDynamicSharedMemorySize, FA_SMEM);

    wconv_kernel<<<80, 256>>>(wq, wk, wv);

    dim3 ggrid(2, 64, BATCH);
    gather_kernel<<<ggrid, 256>>>(x);

    dim3 pggrid(NPTOT / 128, 5);
    projgemm_kernel<<<pggrid, 256, PG_SMEM>>>(bq, bk, bv);

    dim3 fgrid(NPIX / 128, 2, BATCH);
    fattn_kernel<<<fgrid, 256, FA_SMEM>>>();

    epi_kernel<<<(BATCH * 64 * 128 * 128) / 256, 256>>>(x, gamma, out);
}